// round 6
// baseline (speedup 1.0000x reference)
#include <cuda_runtime.h>

#define HH 1024
#define WW 1024
#define NC 128
#define TS 64          // tile is 64x64 pixels
#define NTILES 16      // tiles per dimension
#define NITER 8
#define NREP 16        // accumulator replicas (contention spreading)

// Per-iteration replicated accumulators. g_part[it][r][c], zeroed each launch.
// Iteration it scatters into replica (blockIdx.x & 15); iteration it+1 reads
// the sum over replicas. Final iteration's replicas are folded into d_out.
__device__ float2 g_part[NITER][NREP][NC];

__global__ void init_zero_kernel()
{
    float4 z4 = make_float4(0.f, 0.f, 0.f, 0.f);
    float4* p = (float4*)g_part;
    int n = (int)(sizeof(g_part) / sizeof(float4));
    for (int i = blockIdx.x * blockDim.x + threadIdx.x; i < n;
         i += gridDim.x * blockDim.x)
        p[i] = z4;
}

__global__ void final_reduce_kernel(float2* __restrict__ out)
{
    int c = threadIdx.x;            // 128 threads
    float x = 0.f, y = 0.f;
    #pragma unroll
    for (int r = 0; r < NREP; ++r) {
        float2 v = g_part[NITER - 1][r][c];
        x += v.x; y += v.y;
    }
    out[c] = make_float2(x, y);
}

__global__ __launch_bounds__(256)
void assign_kernel(const float* __restrict__ clusters_in,
                   const float* __restrict__ heat,
                   int it)
{
    __shared__ float  s_warpmin[8];
    __shared__ int    s_cnt[4];
    __shared__ int    s_hslot[256];
    __shared__ int    s_sidx[NC];
    __shared__ float2 s_all[NC];
    __shared__ float2 s_scl[NC];
    __shared__ float2 s_acc[NC];

    const int tid = threadIdx.x;
    const int i0 = blockIdx.y * TS;
    const int j0 = blockIdx.x * TS;

    // ---- hoisted heatmap loads: 4 row-passes x 4 cols per thread ----
    const int rslot = tid >> 4;            // 0..15, covers rows rslot*4..+3
    const int cg    = (tid & 15) << 2;     // 0,4,...,60
    float4 h4[4];
    #pragma unroll
    for (int rp = 0; rp < 4; ++rp)
        h4[rp] = *(const float4*)(heat + (i0 + (rslot << 2) + rp) * WW + j0 + cg);

    s_hslot[tid] = 1 << 30;

    // ---- per-cluster preamble (threads 0..127) ----
    float    cdist2 = 3.4e38f;
    float2   cl = make_float2(0.f, 0.f);
    unsigned hsh = 0;
    if (tid < NC) {
        if (it == 0) {
            cl = ((const float2*)clusters_in)[tid];   // (row, col)
        } else {
            float x = 0.f, y = 0.f;
            #pragma unroll
            for (int r = 0; r < NREP; ++r) {
                float2 v = g_part[it - 1][r][tid];
                x += v.x; y += v.y;
            }
            cl = make_float2(x, y);
        }
        s_all[tid] = cl;
        s_acc[tid] = make_float2(0.f, 0.f);
        float dr = (float)i0 + 31.5f - cl.x;
        float dc = (float)j0 + 31.5f - cl.y;
        cdist2 = __fadd_rn(__fmul_rn(dr, dr), __fmul_rn(dc, dc));
        unsigned hx = __float_as_uint(cl.x), hy = __float_as_uint(cl.y);
        hsh = hx * 2654435761u ^ hy * 40503u;
        hsh = (hsh ^ (hsh >> 16)) & 255u;
    }

    // warp-level min reduction of center distances
    float m = cdist2;
    #pragma unroll
    for (int o = 16; o; o >>= 1)
        m = fminf(m, __shfl_xor_sync(0xffffffffu, m, o));
    if ((tid & 31) == 0)
        s_warpmin[tid >> 5] = m;
    __syncthreads();   // hslot init + warpmin + s_all visible

    if (tid < NC)
        atomicMin(&s_hslot[hsh], tid);

    float mind2 = fminf(fminf(fminf(s_warpmin[0], s_warpmin[1]),
                              fminf(s_warpmin[2], s_warpmin[3])),
                        fminf(fminf(s_warpmin[4], s_warpmin[5]),
                              fminf(s_warpmin[6], s_warpmin[7])));
    __syncthreads();   // hash slots settled

    // Hash dedup: if a LOWER-index cluster has identical coords, drop this one
    // (exact w.r.t. the strict-< argmin tie-break). A hash collision can only
    // MISS a dedup, which is still correct: survivors stay index-sorted, so
    // the lower-index twin always wins strict-<.
    bool uniq = true;
    if (tid < NC) {
        int w = s_hslot[hsh];
        if (w < tid) {
            float2 o = s_all[w];
            uniq = !((o.x == cl.x) & (o.y == cl.y));
        }
    }

    // Survivor criterion: dist(center,c) <= min_dist + 2r (+margin).
    // r = 31.5*sqrt(2) = 44.55; 2r = 89.1; margin absorbs fp rounding.
    float thr  = sqrtf(mind2) + 90.2f;
    bool pred = (tid < NC) && uniq && (cdist2 <= thr * thr);
    unsigned bal = __ballot_sync(0xffffffffu, pred);
    if ((tid & 31) == 0 && tid < NC)
        s_cnt[tid >> 5] = __popc(bal);
    __syncthreads();

    int c0 = s_cnt[0], c1 = s_cnt[1], c2 = s_cnt[2], c3 = s_cnt[3];
    int nsurv = c0 + c1 + c2 + c3;
    if (pred) {
        int w    = tid >> 5;
        int base = (w > 0 ? c0 : 0) + (w > 1 ? c1 : 0) + (w > 2 ? c2 : 0);
        int pos  = base + __popc(bal & ((1u << (tid & 31)) - 1u));
        s_sidx[pos] = tid;    // ascending cluster index -> tie-break preserved
        s_scl[pos]  = cl;
    }
    __syncthreads();

    // ---- pixel phase: 4 row passes, 4 consecutive columns each ----
    const unsigned full = 0xffffffffu;
    const float fj0 = (float)(j0 + cg);
    const float fj1 = fj0 + 1.0f;
    const float fj2 = fj0 + 2.0f;
    const float fj3 = fj0 + 3.0f;

    #pragma unroll
    for (int rp = 0; rp < 4; ++rp) {
        const float fi = (float)(i0 + (rslot << 2) + rp);

        float b0 = 3.4e38f, b1 = 3.4e38f, b2 = 3.4e38f, b3 = 3.4e38f;
        int   s0 = 0, s1 = 0, s2 = 0, s3 = 0;

        for (int s = 0; s < nsurv; ++s) {
            float2 c = s_scl[s];
            float dr  = fi - c.x;
            float dr2 = __fmul_rn(dr, dr);

            // Match reference arithmetic: dr*dr + dc*dc (no fma contraction)
            float dc0 = fj0 - c.y;
            float d20 = fmaxf(__fadd_rn(dr2, __fmul_rn(dc0, dc0)), 1.0f);
            if (d20 < b0) { b0 = d20; s0 = s; }

            float dc1 = fj1 - c.y;
            float d21 = fmaxf(__fadd_rn(dr2, __fmul_rn(dc1, dc1)), 1.0f);
            if (d21 < b1) { b1 = d21; s1 = s; }

            float dc2 = fj2 - c.y;
            float d22 = fmaxf(__fadd_rn(dr2, __fmul_rn(dc2, dc2)), 1.0f);
            if (d22 < b2) { b2 = d22; s2 = s; }

            float dc3 = fj3 - c.y;
            float d23 = fmaxf(__fadd_rn(dr2, __fmul_rn(dc3, dc3)), 1.0f);
            if (d23 < b3) { b3 = d23; s3 = s; }
        }

        float w0 = h4[rp].x * __frsqrt_rn(b0);
        float w1 = h4[rp].y * __frsqrt_rn(b1);
        float w2 = h4[rp].z * __frsqrt_rn(b2);
        float w3 = h4[rp].w * __frsqrt_rn(b3);

        bool same4 = (s0 == s1) & (s0 == s2) & (s0 == s3);
        int  sref  = __shfl_sync(full, s0, 0);
        bool uni   = __all_sync(full, same4 && (s0 == sref));

        if (uni) {
            // whole warp shares one winner: reduce then 2 shared atomics
            float lx = fi * ((w0 + w1) + (w2 + w3));
            float ly = (fj0 * w0 + fj1 * w1) + (fj2 * w2 + fj3 * w3);
            #pragma unroll
            for (int o = 16; o; o >>= 1) {
                lx += __shfl_xor_sync(full, lx, o);
                ly += __shfl_xor_sync(full, ly, o);
            }
            if ((tid & 31) == 0) {
                int ci = s_sidx[sref];
                atomicAdd(&s_acc[ci].x, lx);
                atomicAdd(&s_acc[ci].y, ly);
            }
        } else {
            {
                int ci = s_sidx[s0];
                atomicAdd(&s_acc[ci].x, fi  * w0);
                atomicAdd(&s_acc[ci].y, fj0 * w0);
            }
            {
                int ci = s_sidx[s1];
                atomicAdd(&s_acc[ci].x, fi  * w1);
                atomicAdd(&s_acc[ci].y, fj1 * w1);
            }
            {
                int ci = s_sidx[s2];
                atomicAdd(&s_acc[ci].x, fi  * w2);
                atomicAdd(&s_acc[ci].y, fj2 * w2);
            }
            {
                int ci = s_sidx[s3];
                atomicAdd(&s_acc[ci].x, fi  * w3);
                atomicAdd(&s_acc[ci].y, fj3 * w3);
            }
        }
    }
    __syncthreads();

    // ---- flush nonzero cluster partials to this block's replica ----
    if (tid < NC) {
        float2 v = s_acc[tid];
        float2* dst = g_part[it][blockIdx.x & (NREP - 1)];
        if (v.x != 0.f) atomicAdd(&dst[tid].x, v.x);
        if (v.y != 0.f) atomicAdd(&dst[tid].y, v.y);
    }
}

extern "C" void kernel_launch(void* const* d_in, const int* in_sizes, int n_in,
                              void* d_out, int out_size)
{
    // Identify inputs by size for robustness: clusters = 256 elems, heatmap = 1M.
    const float* clusters = (const float*)d_in[0];
    const float* heat     = (const float*)d_in[1];
    if (in_sizes[0] != NC * 2) {
        clusters = (const float*)d_in[1];
        heat     = (const float*)d_in[0];
    }
    float2* out = (float2*)d_out;

    init_zero_kernel<<<64, 256>>>();

    dim3 grid(NTILES, NTILES);
    for (int it = 0; it < NITER; ++it)
        assign_kernel<<<grid, 256>>>(clusters, heat, it);

    final_reduce_kernel<<<1, NC>>>(out);
}

// round 8
// speedup vs baseline: 1.6602x; 1.6602x over previous
#include <cuda_runtime.h>

#define HH 1024
#define WW 1024
#define NC 128
#define TS 32          // tile is 32x32 pixels
#define NTILES 32      // tiles per dimension
#define NBLK (NTILES * NTILES)
#define NITER 8
#define NREP 16        // accumulator replicas (contention spreading)

// Replicated accumulators + per-iteration deduped candidate lists.
// g_part[it][r][c] : scatter targets (replica r = blockIdx.x & 15)
// g_cl/g_cli[it]   : compacted candidate coords / original indices for iter it
//                    (written by init for it=0, by the tail block of iter it-1)
__device__ float2 g_part[NITER][NREP][NC];
__device__ float2 g_cl[NITER][NC];
__device__ int    g_cli[NITER][NC];
__device__ int    g_ncl[NITER];
__device__ int    g_cnt[NITER];

__device__ __forceinline__ unsigned coord_hash(float2 c)
{
    unsigned hx = __float_as_uint(c.x), hy = __float_as_uint(c.y);
    unsigned h = hx * 2654435761u ^ hy * 40503u;
    return (h ^ (h >> 16)) & 255u;
}

__global__ void init_kernel(const float* __restrict__ clusters)
{
    __shared__ int    s_hslot[256];
    __shared__ int    s_cnt4[4];
    __shared__ float2 s_all[NC];

    const int tid = threadIdx.x;   // 256 threads

    // zero the replica accumulators + counters
    float4 z4 = make_float4(0.f, 0.f, 0.f, 0.f);
    float4* p = (float4*)g_part;
    int n = (int)(sizeof(g_part) / sizeof(float4));
    for (int i = tid; i < n; i += 256) p[i] = z4;
    if (tid < NITER) g_cnt[tid] = 0;

    // dedup + compact the input clusters into g_cl[0]
    s_hslot[tid] = 1 << 30;
    float2   cl = make_float2(0.f, 0.f);
    unsigned hsh = 0;
    if (tid < NC) {
        cl = ((const float2*)clusters)[tid];
        s_all[tid] = cl;
        hsh = coord_hash(cl);
    }
    __syncthreads();
    if (tid < NC) atomicMin(&s_hslot[hsh], tid);
    __syncthreads();

    bool uniq = false;
    if (tid < NC) {
        uniq = true;
        int w = s_hslot[hsh];
        if (w < tid) {
            float2 o = s_all[w];
            uniq = !((o.x == cl.x) & (o.y == cl.y));
        }
    }
    unsigned bal = __ballot_sync(0xffffffffu, uniq);
    if ((tid & 31) == 0 && tid < NC) s_cnt4[tid >> 5] = __popc(bal);
    __syncthreads();
    int c0 = s_cnt4[0], c1 = s_cnt4[1], c2 = s_cnt4[2], c3 = s_cnt4[3];
    if (uniq) {
        int w = tid >> 5;
        int base = (w > 0 ? c0 : 0) + (w > 1 ? c1 : 0) + (w > 2 ? c2 : 0);
        int pos = base + __popc(bal & ((1u << (tid & 31)) - 1u));
        g_cl[0][pos]  = cl;     // ascending original index -> tie-break kept
        g_cli[0][pos] = tid;
    }
    if (tid == 0) g_ncl[0] = c0 + c1 + c2 + c3;
}

__global__ void final_reduce_kernel(float2* __restrict__ out)
{
    int c = threadIdx.x;            // 128 threads
    float x = 0.f, y = 0.f;
    #pragma unroll
    for (int r = 0; r < NREP; ++r) {
        float2 v = g_part[NITER - 1][r][c];
        x += v.x; y += v.y;
    }
    out[c] = make_float2(x, y);
}

__global__ __launch_bounds__(256)
void assign_kernel(const float* __restrict__ heat, int it)
{
    __shared__ float  s_warpmin[4];
    __shared__ int    s_cnt4[4];
    __shared__ int    s_hslot[256];
    __shared__ int    s_sidx[NC];
    __shared__ float2 s_scl[NC];
    __shared__ float2 s_acc[NC];
    __shared__ int    s_last;

    const int tid = threadIdx.x;
    const int i0 = blockIdx.y * TS;
    const int j0 = blockIdx.x * TS;

    // ---- hoisted heatmap load: 4 consecutive cols of one row per thread ----
    const int prow = tid >> 3;            // 0..31
    const int pcg  = (tid & 7) << 2;      // 0,4,...,28
    const float4 h4 = *(const float4*)(heat + (i0 + prow) * WW + j0 + pcg);

    const int ncl = g_ncl[it];

    // ---- candidate preamble: distance from tile center (tid < ncl) ----
    float  cdist2 = 3.4e38f;
    float2 cl = make_float2(0.f, 0.f);
    int    cidx = 0;
    if (tid < ncl) {
        cl   = g_cl[it][tid];             // pre-deduped, index-sorted
        cidx = g_cli[it][tid];
        float dr = (float)i0 + 15.5f - cl.x;
        float dc = (float)j0 + 15.5f - cl.y;
        cdist2 = __fadd_rn(__fmul_rn(dr, dr), __fmul_rn(dc, dc));
    }
    if (tid < NC) s_acc[tid] = make_float2(0.f, 0.f);

    // warp-level min of center distances (warps 0..3 hold all candidates)
    float m = cdist2;
    #pragma unroll
    for (int o = 16; o; o >>= 1)
        m = fminf(m, __shfl_xor_sync(0xffffffffu, m, o));
    if ((tid & 31) == 0 && tid < NC) s_warpmin[tid >> 5] = m;
    __syncthreads();
    float mind2 = fminf(fminf(s_warpmin[0], s_warpmin[1]),
                        fminf(s_warpmin[2], s_warpmin[3]));

    // Survivor criterion: dist(center,c) <= min_dist + 2r (+margin).
    // r = 15.5*sqrt(2) = 21.92; 2r = 43.84; margin absorbs fp rounding.
    // (Excluded candidates can never win OR tie -> exact.)
    float thr = sqrtf(mind2) + 44.9f;
    bool pred = (tid < ncl) && (cdist2 <= thr * thr);
    unsigned bal = __ballot_sync(0xffffffffu, pred);
    if ((tid & 31) == 0 && tid < NC) s_cnt4[tid >> 5] = __popc(bal);
    __syncthreads();

    int c0 = s_cnt4[0], c1 = s_cnt4[1], c2 = s_cnt4[2], c3 = s_cnt4[3];
    int nsurv = c0 + c1 + c2 + c3;
    if (pred) {
        int w    = tid >> 5;
        int base = (w > 0 ? c0 : 0) + (w > 1 ? c1 : 0) + (w > 2 ? c2 : 0);
        int pos  = base + __popc(bal & ((1u << (tid & 31)) - 1u));
        s_sidx[pos] = cidx;   // ascending original index -> tie-break kept
        s_scl[pos]  = cl;
    }
    __syncthreads();

    // ---- pixel phase: each thread handles 4 consecutive cols of one row ----
    const unsigned full = 0xffffffffu;
    const float fi  = (float)(i0 + prow);
    const float fj0 = (float)(j0 + pcg);
    const float fj1 = fj0 + 1.0f;
    const float fj2 = fj0 + 2.0f;
    const float fj3 = fj0 + 3.0f;

    float b0 = 3.4e38f, b1 = 3.4e38f, b2 = 3.4e38f, b3 = 3.4e38f;
    int   s0 = 0, s1 = 0, s2 = 0, s3 = 0;

    for (int s = 0; s < nsurv; ++s) {
        float2 c = s_scl[s];
        float dr  = fi - c.x;
        float dr2 = __fmul_rn(dr, dr);

        // Match reference arithmetic: dr*dr + dc*dc (no fma contraction)
        float dc0 = fj0 - c.y;
        float d20 = fmaxf(__fadd_rn(dr2, __fmul_rn(dc0, dc0)), 1.0f);
        if (d20 < b0) { b0 = d20; s0 = s; }

        float dc1 = fj1 - c.y;
        float d21 = fmaxf(__fadd_rn(dr2, __fmul_rn(dc1, dc1)), 1.0f);
        if (d21 < b1) { b1 = d21; s1 = s; }

        float dc2 = fj2 - c.y;
        float d22 = fmaxf(__fadd_rn(dr2, __fmul_rn(dc2, dc2)), 1.0f);
        if (d22 < b2) { b2 = d22; s2 = s; }

        float dc3 = fj3 - c.y;
        float d23 = fmaxf(__fadd_rn(dr2, __fmul_rn(dc3, dc3)), 1.0f);
        if (d23 < b3) { b3 = d23; s3 = s; }
    }

    float w0 = h4.x * __frsqrt_rn(b0);
    float w1 = h4.y * __frsqrt_rn(b1);
    float w2 = h4.z * __frsqrt_rn(b2);
    float w3 = h4.w * __frsqrt_rn(b3);

    bool same4 = (s0 == s1) & (s0 == s2) & (s0 == s3);
    int  sref  = __shfl_sync(full, s0, 0);
    bool uni   = __all_sync(full, same4 && (s0 == sref));

    if (uni) {
        // whole warp shares one winner: reduce then 2 shared atomics
        float lx = fi * ((w0 + w1) + (w2 + w3));
        float ly = (fj0 * w0 + fj1 * w1) + (fj2 * w2 + fj3 * w3);
        #pragma unroll
        for (int o = 16; o; o >>= 1) {
            lx += __shfl_xor_sync(full, lx, o);
            ly += __shfl_xor_sync(full, ly, o);
        }
        if ((tid & 31) == 0) {
            int ci = s_sidx[sref];
            atomicAdd(&s_acc[ci].x, lx);
            atomicAdd(&s_acc[ci].y, ly);
        }
    } else {
        { int ci = s_sidx[s0];
          atomicAdd(&s_acc[ci].x, fi  * w0); atomicAdd(&s_acc[ci].y, fj0 * w0); }
        { int ci = s_sidx[s1];
          atomicAdd(&s_acc[ci].x, fi  * w1); atomicAdd(&s_acc[ci].y, fj1 * w1); }
        { int ci = s_sidx[s2];
          atomicAdd(&s_acc[ci].x, fi  * w2); atomicAdd(&s_acc[ci].y, fj2 * w2); }
        { int ci = s_sidx[s3];
          atomicAdd(&s_acc[ci].x, fi  * w3); atomicAdd(&s_acc[ci].y, fj3 * w3); }
    }
    __syncthreads();

    // ---- flush nonzero cluster partials to this block's replica ----
    if (tid < NC) {
        float2 v = s_acc[tid];
        float2* dst = g_part[it][blockIdx.x & (NREP - 1)];
        if (v.x != 0.f) atomicAdd(&dst[tid].x, v.x);
        if (v.y != 0.f) atomicAdd(&dst[tid].y, v.y);
    }

    // ---- tail: last finishing block builds next iteration's candidates ----
    if (it + 1 < NITER) {
        if (tid == 0) {
            __threadfence();                    // make our flush visible first
            int v = atomicAdd(&g_cnt[it], 1);
            s_last = (v == NBLK - 1);
        }
        __syncthreads();
        if (s_last) {
            __threadfence();                    // acquire all blocks' flushes

            s_hslot[tid] = 1 << 30;
            float2   cs  = make_float2(0.f, 0.f);
            unsigned hsh = 0;
            if (tid < NC) {
                float x = 0.f, y = 0.f;
                #pragma unroll
                for (int r = 0; r < NREP; ++r) {
                    float2 v = g_part[it][r][tid];
                    x += v.x; y += v.y;
                }
                cs = make_float2(x, y);
                s_scl[tid] = cs;                // reuse as coord store
                hsh = coord_hash(cs);
            }
            __syncthreads();
            if (tid < NC) atomicMin(&s_hslot[hsh], tid);
            __syncthreads();

            // Hash dedup: identical coords at a LOWER index -> drop (exact
            // w.r.t. strict-< argmin tie-break; a hash collision can only
            // MISS a dedup, which is harmless).
            bool uniq = false;
            if (tid < NC) {
                uniq = true;
                int w = s_hslot[hsh];
                if (w < tid) {
                    float2 o = s_scl[w];
                    uniq = !((o.x == cs.x) & (o.y == cs.y));
                }
            }
            unsigned b2 = __ballot_sync(full, uniq);
            if ((tid & 31) == 0 && tid < NC) s_cnt4[tid >> 5] = __popc(b2);
            __syncthreads();
            int d0 = s_cnt4[0], d1 = s_cnt4[1], d2 = s_cnt4[2], d3 = s_cnt4[3];
            if (uniq) {
                int w = tid >> 5;
                int base = (w > 0 ? d0 : 0) + (w > 1 ? d1 : 0) + (w > 2 ? d2 : 0);
                int pos = base + __popc(b2 & ((1u << (tid & 31)) - 1u));
                g_cl[it + 1][pos]  = cs;
                g_cli[it + 1][pos] = tid;
            }
            if (tid == 0) g_ncl[it + 1] = d0 + d1 + d2 + d3;
        }
    }
}

extern "C" void kernel_launch(void* const* d_in, const int* in_sizes, int n_in,
                              void* d_out, int out_size)
{
    // Identify inputs by size for robustness: clusters = 256 elems, heatmap = 1M.
    const float* clusters = (const float*)d_in[0];
    const float* heat     = (const float*)d_in[1];
    if (in_sizes[0] != NC * 2) {
        clusters = (const float*)d_in[1];
        heat     = (const float*)d_in[0];
    }
    float2* out = (float2*)d_out;

    init_kernel<<<1, 256>>>(clusters);

    dim3 grid(NTILES, NTILES);
    for (int it = 0; it < NITER; ++it)
        assign_kernel<<<grid, 256>>>(heat, it);

    final_reduce_kernel<<<1, NC>>>(out);
}